// round 17
// baseline (speedup 1.0000x reference)
#include <cuda_runtime.h>
#include <cuda_bf16.h>
#include <stdint.h>

// ---------------------------------------------------------------------------
// Hodge1LapEdgeEncoder
//
// Output (float32): [0,P) idx rows | [P,2P) idx cols | [2P,2P+P*D) dense vals
//   dense[slot,:] = padding + sum_{e: slot(e)==slot} (edge_attr[e] + pestat[e,0]*fc_w)
//   slot(e) = u*n + (v%n),  u = ei[0,e], v = ei[1,e]
//   Edges of graph g occupy the contiguous range [g*epg, (g+1)*epg).
//
// Tier 1: ONE kernel. Graph g owns a contiguous group of BPG blocks.
//   Each block: init its slice of g's dense region -> arrive on done[g] ->
//   spin till all BPG arrived (co-resident by dispatch order; deadlock-free)
//   -> scatter its share of g's edges onto the L2-hot region. idx blocks lead.
// Tier 2: proven serial path (init4 + idx/scatter, 20.4us).
// Tier 3: generic scalar path.
// ---------------------------------------------------------------------------

#define TB 256
#define IPT 4              // float4 stores per init thread
#define MAXB 1024          // max graphs supported by flag arrays

__device__ int g_done[MAXB];   // init-arrivals per graph (.bss zero)
__device__ int g_cons[MAXB];   // scatter-completions per graph

__device__ __forceinline__ void red_add_v4(float* dst, float4 r)
{
#if __CUDA_ARCH__ >= 900
    asm volatile("red.global.add.v4.f32 [%0], {%1, %2, %3, %4};"
                 :: "l"(dst), "f"(r.x), "f"(r.y), "f"(r.z), "f"(r.w)
                 : "memory");
#else
    atomicAdd(dst + 0, r.x); atomicAdd(dst + 1, r.y);
    atomicAdd(dst + 2, r.z); atomicAdd(dst + 3, r.w);
#endif
}

// ===========================================================================
// Tier 1: per-graph self-synchronized pipeline kernel.
// Grid = [idxBlocks][B * BPG].
// ===========================================================================
__global__ void k_graph_pipe(float* __restrict__ out, long long P,
                             const int*    __restrict__ ei,      // [2, E]
                             const float*  __restrict__ pestat,  // [E, K]
                             const float4* __restrict__ ea4,     // [E, D4]
                             const float4* __restrict__ w4,      // [D4]
                             const float4* __restrict__ pad4,    // [D4]
                             float* __restrict__ val,
                             int E, int K, int s4, int sn,
                             int idxBlocks, int BPG,
                             long long g4,          // float4s per graph region
                             int epg)               // edges per graph
{
    const int tid = threadIdx.x;
    int bid = blockIdx.x;
    const int D4m = (1 << s4) - 1;

    if (bid < idxBlocks) {
        // ---- idx pattern, float4-vectorized (n % 4 == 0 by host guard) ----
        long long P4 = P >> 2;
        long long t = (long long)bid * TB + tid;
        if (t >= P4) return;
        long long q = t << 2;
        int nm1  = (1 << sn) - 1;
        long long nnm1 = ((long long)1 << (2 * sn)) - 1;
        int b   = (int)(q >> (2 * sn));
        int rem = (int)(q & nnm1);
        int i   = rem >> sn;
        int j   = rem & nm1;
        float rv = (float)((b << sn) + i);
        float cv = (float)((b << sn) + j);
        ((float4*)out)[t]       = make_float4(rv, rv, rv, rv);
        ((float4*)(out + P))[t] = make_float4(cv, cv + 1.f, cv + 2.f, cv + 3.f);
        return;
    }
    bid -= idxBlocks;

    const int g = bid / BPG;          // graph id
    const int j = bid - g * BPG;      // block index within graph group

    // ---- Phase 1: init this block's slice of graph g's dense region ----
    {
        float4* base4 = ((float4*)val) + (long long)g * g4;
        long long start = (long long)j * (TB * IPT) + tid;
        float4 pv = __ldg(&pad4[tid & D4m]);      // TB % D4 == 0
        #pragma unroll
        for (int k = 0; k < IPT; k++) {
            long long v = start + (long long)k * TB;
            if (v < g4) base4[v] = pv;
        }
    }
    __threadfence();
    __syncthreads();
    if (tid == 0) {
        atomicAdd(&g_done[g], 1);
        while (*((volatile int*)&g_done[g]) < BPG)
            __nanosleep(64);
    }
    __syncthreads();
    __threadfence();

    // ---- Phase 2: scatter this block's share of graph g's edges ----
    {
        const int items = epg << s4;              // work items for this graph
        for (int t = j * TB + tid; t < items; t += BPG * TB) {
            int e = g * epg + (t >> s4);
            int c = t & D4m;

            int u  = __ldg(&ei[e]);
            int rv = __ldg(&ei[E + e]) & ((1 << sn) - 1);
            float  p = __ldg(&pestat[(long long)e * K]);
            float4 a = __ldg(&ea4[((long long)e << s4) + c]);
            float4 w = __ldg(&w4[c]);
            float4 rr = make_float4(a.x + p * w.x, a.y + p * w.y,
                                    a.z + p * w.z, a.w + p * w.w);
            long long slot = ((long long)u << sn) | rv;
            red_add_v4(val + (slot << (s4 + 2)) + (c << 2), rr);
        }
    }

    // ---- Phase 3: last block of the graph resets flags (replay-safe) ----
    __syncthreads();
    if (tid == 0) {
        int c = atomicAdd(&g_cons[g], 1);
        if (c == BPG - 1) {
            atomicExch(&g_done[g], 0);
            atomicExch(&g_cons[g], 0);
        }
    }
}

// ===========================================================================
// Tier 2: proven serial path (R10): init + fused idx/scatter.
// ===========================================================================
__global__ void k_init4(float4* __restrict__ val4,
                        const float4* __restrict__ pad4,
                        long long V4, int D4)
{
    long long base = (long long)blockIdx.x * (TB * IPT) + threadIdx.x;
    float4 pv = __ldg(&pad4[(int)threadIdx.x & (D4 - 1)]);
    #pragma unroll
    for (int k = 0; k < IPT; k++) {
        long long v = base + (long long)k * TB;
        if (v < V4) val4[v] = pv;
    }
}

__global__ void k_idx_scatter(float* __restrict__ out, long long P,
                              const int* __restrict__ ei,
                              const float* __restrict__ pestat,
                              const float4* __restrict__ ea4,
                              const float4* __restrict__ w4,
                              float* __restrict__ val,
                              int E, int K, int s4, int sn,
                              int idxBlocks)
{
    const int tid = threadIdx.x;
    const int bid = blockIdx.x;

    if (bid < idxBlocks) {
        long long P4 = P >> 2;
        long long t = (long long)bid * TB + tid;
        if (t >= P4) return;
        long long q = t << 2;
        int nm1  = (1 << sn) - 1;
        long long nnm1 = ((long long)1 << (2 * sn)) - 1;
        int b   = (int)(q >> (2 * sn));
        int rem = (int)(q & nnm1);
        int i   = rem >> sn;
        int j   = rem & nm1;
        float rv = (float)((b << sn) + i);
        float cv = (float)((b << sn) + j);
        ((float4*)out)[t]       = make_float4(rv, rv, rv, rv);
        ((float4*)(out + P))[t] = make_float4(cv, cv + 1.f, cv + 2.f, cv + 3.f);
        return;
    }

    int t = (bid - idxBlocks) * TB + tid;
    if (t >= (E << s4)) return;
    int e = t >> s4;
    int c = t & ((1 << s4) - 1);

    int u  = __ldg(&ei[e]);
    int rv = __ldg(&ei[E + e]) & ((1 << sn) - 1);
    float  p = __ldg(&pestat[(long long)e * K]);
    float4 a = __ldg(&ea4[((long long)e << s4) + c]);
    float4 w = __ldg(&w4[c]);
    float4 rr = make_float4(a.x + p * w.x, a.y + p * w.y,
                            a.z + p * w.z, a.w + p * w.w);
    long long slot = ((long long)u << sn) | rv;
    red_add_v4(val + (slot << (s4 + 2)) + (c << 2), rr);
}

// ===========================================================================
// Tier 3: fully generic fallbacks.
// ===========================================================================
__global__ void k_init_fused_s(float* __restrict__ out, const float* __restrict__ pad,
                               long long P, int n, int D)
{
    long long totalI = P;
    long long tot = P + P * (long long)D;
    float* val = out + 2 * P;
    long long stride = (long long)gridDim.x * blockDim.x;
    for (long long t = (long long)blockIdx.x * blockDim.x + threadIdx.x;
         t < tot; t += stride) {
        if (t < totalI) {
            long long nn = (long long)n * n;
            int b   = (int)(t / nn);
            int rem = (int)(t - (long long)b * nn);
            int i   = rem / n;
            int j   = rem - i * n;
            out[t]     = (float)(b * n + i);
            out[P + t] = (float)(b * n + j);
        } else {
            long long v = t - totalI;
            val[v] = __ldg(&pad[(int)(v % D)]);
        }
    }
}

__global__ void k_scatter_s(const int* __restrict__ ei, const float* __restrict__ pestat,
                            const float* __restrict__ ea, const float* __restrict__ w,
                            float* __restrict__ val, int E, int K, int D, int n)
{
    long long tot = (long long)E * D;
    long long stride = (long long)gridDim.x * blockDim.x;
    for (long long t = (long long)blockIdx.x * blockDim.x + threadIdx.x;
         t < tot; t += stride) {
        int e = (int)(t / D);
        int d = (int)(t - (long long)e * D);
        int u = __ldg(&ei[e]);
        int v = __ldg(&ei[E + e]);
        int g  = u / n;
        int ru = u - g * n;
        int rv = v % n;
        float p = __ldg(&pestat[(long long)e * K]);
        float x = ea[(long long)e * D + d] + p * __ldg(&w[d]);
        long long base = (((long long)g * n + ru) * n + rv) * (long long)D + d;
        atomicAdd(val + base, x);
    }
}

// ===========================================================================

static inline bool is_pow2(int x) { return x > 0 && (x & (x - 1)) == 0; }
static inline int  ilog2(int x)   { int s = 0; while ((1 << s) < x) s++; return s; }
static inline int grid_for(long long work, int tb)
{
    long long g = (work + tb - 1) / tb;
    if (g > 1048576) g = 1048576;
    if (g < 1) g = 1;
    return (int)g;
}

extern "C" void kernel_launch(void* const* d_in, const int* in_sizes, int n_in,
                              void* d_out, int out_size)
{
    // metadata order: edge_index, pestat, edge_attr, batch, fc_w, padding
    const int*   ei     = (const int*)  d_in[0];
    const float* pestat = (const float*)d_in[1];
    const float* ea     = (const float*)d_in[2];
    const float* fc_w   = (const float*)d_in[4];
    const float* pad    = (const float*)d_in[5];

    const int E = in_sizes[0] / 2;
    const int K = in_sizes[1] / E;
    const int D = in_sizes[2] / E;
    const int N = in_sizes[3];                            // dense rows = B*n
    const long long P = (long long)out_size / (D + 2);    // slots = B*n*n
    const int n = (int)(P / N);
    const int B = (n > 0) ? N / n : 0;

    float* out = (float*)d_out;
    float* val = out + 2 * P;
    const int D4 = D / 4;

    const bool pow2ok = (D % 4 == 0) && (n % 4 == 0) &&
                        is_pow2(n) && is_pow2(D4) && D4 <= 256 &&
                        ((long long)E * D4 < (1LL << 30));

    // Per-graph pipeline feasibility: contiguous per-graph edges, flags fit,
    // and the graph's block group fits comfortably in one residency window.
    const long long g4  = (B > 0) ? (P / B) * (long long)D4 : 0;  // float4s/graph
    const int epg       = (B > 0) ? E / B : 0;
    int BPG = 0;
    if (B > 0) {
        long long bInit = (g4 + (long long)TB * IPT - 1) / ((long long)TB * IPT);
        long long bScat = (((long long)epg << ilog2(D4 > 0 ? D4 : 1)) + TB - 1) / TB;
        BPG = (int)(bInit > bScat ? bInit : bScat);
    }
    const bool pipeok = pow2ok && B > 0 && B <= MAXB &&
                        (E % B == 0) && ((long long)N * n == P) &&
                        (P % B == 0) && BPG >= 1 && BPG <= 512;

    if (pipeok) {
        const int sn = ilog2(n);
        const int s4 = ilog2(D4);
        const int idxBlocks = (int)(((P >> 2) + TB - 1) / TB);
        const int grid = idxBlocks + B * BPG;

        k_graph_pipe<<<grid, TB>>>(out, P, ei, pestat,
                                   (const float4*)ea, (const float4*)fc_w,
                                   (const float4*)pad, val,
                                   E, K, s4, sn,
                                   idxBlocks, BPG, g4, epg);
    } else if (pow2ok) {
        const int sn = ilog2(n);
        const int s4 = ilog2(D4);
        const long long V4 = P * (long long)D4;

        long long initBlocks = (V4 + (long long)TB * IPT - 1) / ((long long)TB * IPT);
        k_init4<<<(int)initBlocks, TB>>>((float4*)val, (const float4*)pad,
                                         V4, D4);

        const int idxBlocks  = (int)(((P >> 2) + TB - 1) / TB);
        const int scatBlocks = (int)(((long long)(E << s4) + TB - 1) / TB);
        k_idx_scatter<<<idxBlocks + scatBlocks, TB>>>(out, P, ei, pestat,
                                                      (const float4*)ea,
                                                      (const float4*)fc_w,
                                                      val, E, K, s4, sn,
                                                      idxBlocks);
    } else {
        long long tot = P + P * (long long)D;
        k_init_fused_s<<<grid_for(tot, TB), TB>>>(out, pad, P, n, D);
        long long st = (long long)E * D;
        k_scatter_s<<<grid_for(st, TB), TB>>>(ei, pestat, ea, fc_w, val,
                                              E, K, D, n);
    }
}